// round 3
// baseline (speedup 1.0000x reference)
#include <cuda_runtime.h>
#include <cuda_bf16.h>

// loss_i = logsumexp(x_i) - dot(w_raw(. - t_i), x_i) / S(t_i)
// w_raw(d) = MAIN (d==0), BASE + UB*2^-d (d>0), BASE (d<0)
// S(t) = MAIN + 8*BASE + UB*(1 - 2^{t-8})

static constexpr int   NUM_CLASSES = 9;
static constexpr float BASE_W = 0.1f / 9.0f;
static constexpr float MAIN_W = 1.0f - 0.1f - 0.2f;   // 0.7
static constexpr float UB     = 0.2f;
static constexpr int   BATCH  = 4000000;
static constexpr int   BLOCK  = 256;
static constexpr int   ROWS_PER_TILE = 1024;          // 4 rows/thread
static constexpr int   GRID   = (BATCH + ROWS_PER_TILE - 1) / ROWS_PER_TILE;  // 3907

__device__ float g_partials[GRID];
__device__ int   g_count = 0;

// exact power of two 2^(-e) for 0 <= e <= 8, via exponent bits (no MUFU)
__device__ __forceinline__ float exp2_neg(int e) {
    return __uint_as_float((unsigned)(127 - e) << 23);
}

__global__ __launch_bounds__(BLOCK)
void ce_fused_kernel(const float* __restrict__ logits,
                     const int*   __restrict__ targets,
                     float*       __restrict__ out) {
    __shared__ float sx[ROWS_PER_TILE * NUM_CLASSES];   // 36 KB, row stride 9 (odd -> no bank conflicts)
    __shared__ float red[BLOCK];
    __shared__ int   s_last;

    const int tid  = threadIdx.x;
    const int tile = blockIdx.x;
    const int frow = tile * ROWS_PER_TILE;
    const int rows = min(ROWS_PER_TILE, BATCH - frow);  // 1024, or 256 on last tile

    // ---- Stage tile: fully coalesced float4 loads ----
    // frow*9 is always divisible by 4 (frow multiple of 1024), rows*9 too (rows multiple of 256).
    const float4* g4 = (const float4*)logits + (size_t)frow * NUM_CLASSES / 4;
    float4*       s4 = (float4*)sx;
    const int nflt4  = rows * NUM_CLASSES / 4;          // 2304 full / 576 partial
    #pragma unroll
    for (int j = 0; j < ROWS_PER_TILE * NUM_CLASSES / 4 / BLOCK; j++) {  // 9 iters
        const int i = j * BLOCK + tid;
        if (i < nflt4) s4[i] = g4[i];
    }
    __syncthreads();

    // ---- Per-row loss, 4 interleaved rows/thread (lane stride 9 floats in smem) ----
    float acc = 0.0f;
    #pragma unroll
    for (int k = 0; k < ROWS_PER_TILE / BLOCK; k++) {
        const int l = tid + k * BLOCK;
        if (l < rows) {
            const float* row = sx + l * NUM_CLASSES;
            float x[NUM_CLASSES];
            #pragma unroll
            for (int c = 0; c < NUM_CLASSES; c++) x[c] = row[c];
            const int t = __ldg(targets + frow + l);

            // logsumexp
            float m = x[0];
            #pragma unroll
            for (int c = 1; c < NUM_CLASSES; c++) m = fmaxf(m, x[c]);
            float se = 0.0f;
            #pragma unroll
            for (int c = 0; c < NUM_CLASSES; c++) se += __expf(x[c] - m);
            const float lse = m + __logf(se);

            // dot(w_raw, x)
            float dot = 0.0f;
            #pragma unroll
            for (int c = 0; c < NUM_CLASSES; c++) {
                const int d = c - t;
                float w;
                if (d == 0)      w = MAIN_W;
                else if (d > 0)  w = BASE_W + UB * exp2_neg(d);
                else             w = BASE_W;
                dot = fmaf(w, x[c], dot);
            }

            const float S = MAIN_W + 8.0f * BASE_W + UB * (1.0f - exp2_neg(8 - t));
            acc += lse - dot / S;
        }
    }

    // ---- Deterministic block tree-reduce ----
    red[tid] = acc;
    __syncthreads();
    #pragma unroll
    for (int s = BLOCK / 2; s > 0; s >>= 1) {
        if (tid < s) red[tid] += red[tid + s];
        __syncthreads();
    }

    // ---- Last-block-done final reduction (fixed read order -> deterministic) ----
    if (tid == 0) {
        g_partials[blockIdx.x] = red[0];
        __threadfence();
        const int old = atomicAdd(&g_count, 1);
        s_last = (old == GRID - 1);
    }
    __syncthreads();

    if (s_last) {
        __threadfence();  // acquire: all partials visible
        float a = 0.0f;
        for (int i = tid; i < GRID; i += BLOCK) a += g_partials[i];
        red[tid] = a;
        __syncthreads();
        #pragma unroll
        for (int s = BLOCK / 2; s > 0; s >>= 1) {
            if (tid < s) red[tid] += red[tid + s];
            __syncthreads();
        }
        if (tid == 0) {
            out[0]  = red[0] * (1.0f / (float)BATCH);
            g_count = 0;   // reset for next graph replay
        }
    }
}

extern "C" void kernel_launch(void* const* d_in, const int* in_sizes, int n_in,
                              void* d_out, int out_size) {
    const float* logits  = (const float*)d_in[0];
    const int*   targets = (const int*)d_in[1];
    float*       out     = (float*)d_out;
    (void)in_sizes; (void)n_in; (void)out_size;

    ce_fused_kernel<<<GRID, BLOCK>>>(logits, targets, out);
}

// round 6
// speedup vs baseline: 1.3367x; 1.3367x over previous
#include <cuda_runtime.h>
#include <cuda_bf16.h>

// loss_i = logsumexp(x_i) - dot(w_raw(. - t_i), x_i) / S(t_i)
// dot = BASE*sum(x) + (MAIN-BASE)*x_t + UB*G(t),  G(t) = sum_{c>t} 2^{t-c} x_c
// S(t) = MAIN + 8*BASE + UB*(1 - 2^{t-8})

static constexpr int   NUM_CLASSES = 9;
static constexpr float BASE_W = 0.1f / 9.0f;
static constexpr float MAIN_W = 0.7f;
static constexpr float UB     = 0.2f;
static constexpr int   BATCH  = 4000000;
static constexpr int   BLOCK  = 256;
static constexpr int   WARPS  = BLOCK / 32;
static constexpr int   TILE   = 32;                    // rows per warp-tile
static constexpr int   NTILES = BATCH / TILE;          // 125000 exactly
static constexpr int   GRID   = 1024;
static constexpr int   NWARPS = GRID * WARPS;          // 8192

__device__ float g_partials[GRID];
__device__ int   g_count = 0;

__global__ __launch_bounds__(BLOCK)
void ce_fused_kernel(const float* __restrict__ logits,
                     const int*   __restrict__ targets,
                     float*       __restrict__ out) {
    // per-warp double-buffered tiles: 32 rows x 9 floats = 1152B (= 9 x 128B lines)
    __shared__ float stage[WARPS][2][TILE * NUM_CLASSES];
    __shared__ float redw[WARPS];
    __shared__ float red2[BLOCK];
    __shared__ int   s_last;

    const int tid  = threadIdx.x;
    const int lane = tid & 31;
    const int w    = tid >> 5;

    float acc = 0.0f;

    // prologue prefetch (gw < NTILES always: NWARPS=8192 << NTILES=125000)
    int   t = blockIdx.x * WARPS + w;
    float r[NUM_CLASSES];
    {
        const float* p = logits + (size_t)t * (TILE * NUM_CLASSES);
        #pragma unroll
        for (int j = 0; j < NUM_CLASSES; j++) r[j] = __ldg(p + j * 32 + lane); // coalesced: 1 wf each
    }
    int tg = __ldg(targets + t * TILE + lane);

    int cur = 0;
    while (t < NTILES) {
        float* buf = stage[w][cur];
        #pragma unroll
        for (int j = 0; j < NUM_CLASSES; j++) buf[j * 32 + lane] = r[j];  // coalesced STS
        const int myt = tg;
        __syncwarp();

        // prefetch next tile while computing this one
        const int tn = t + NWARPS;
        if (tn < NTILES) {
            const float* p = logits + (size_t)tn * (TILE * NUM_CLASSES);
            #pragma unroll
            for (int j = 0; j < NUM_CLASSES; j++) r[j] = __ldg(p + j * 32 + lane);
            tg = __ldg(targets + tn * TILE + lane);
        }

        // each lane computes one row from smem (stride 9 -> conflict-free)
        float x[NUM_CLASSES];
        const float* rowp = buf + lane * NUM_CLASSES;
        #pragma unroll
        for (int c = 0; c < NUM_CLASSES; c++) x[c] = rowp[c];

        float m = x[0];
        #pragma unroll
        for (int c = 1; c < NUM_CLASSES; c++) m = fmaxf(m, x[c]);
        float se = 0.0f, sumx = 0.0f;
        #pragma unroll
        for (int c = 0; c < NUM_CLASSES; c++) {
            se   += __expf(x[c] - m);
            sumx += x[c];
        }
        const float lse = m + __logf(se);

        // suffix geometric scan: after processing class c, g = G(c-1)
        float g = 0.0f, gt = 0.0f, xt = 0.0f;
        #pragma unroll
        for (int c = NUM_CLASSES - 1; c >= 0; c--) {
            if (c == myt) { gt = g; xt = x[c]; }
            g = 0.5f * (g + x[c]);
        }

        const float dot = fmaf(BASE_W, sumx, fmaf(MAIN_W - BASE_W, xt, UB * gt));
        // 2^(t-8) exactly via exponent bits
        const float p2  = __uint_as_float((unsigned)(119 + myt) << 23);
        const float S   = MAIN_W + 8.0f * BASE_W + UB * (1.0f - p2);
        acc += lse - __fdividef(dot, S);

        t = tn; cur ^= 1;
    }

    // deterministic warp butterfly reduce
    #pragma unroll
    for (int off = 16; off; off >>= 1) acc += __shfl_xor_sync(0xFFFFFFFFu, acc, off);
    if (lane == 0) redw[w] = acc;
    __syncthreads();

    if (tid == 0) {
        float b = 0.0f;
        #pragma unroll
        for (int i = 0; i < WARPS; i++) b += redw[i];
        g_partials[blockIdx.x] = b;
        __threadfence();
        s_last = (atomicAdd(&g_count, 1) == GRID - 1);
    }
    __syncthreads();

    if (s_last) {
        __threadfence();  // acquire: all partials visible
        float a = 0.0f;
        for (int i = tid; i < GRID; i += BLOCK) a += g_partials[i];
        red2[tid] = a;
        __syncthreads();
        #pragma unroll
        for (int s = BLOCK / 2; s > 0; s >>= 1) {
            if (tid < s) red2[tid] += red2[tid + s];
            __syncthreads();
        }
        if (tid == 0) {
            out[0]  = red2[0] * (1.0f / (float)BATCH);
            g_count = 0;   // reset for next graph replay
        }
    }
}

extern "C" void kernel_launch(void* const* d_in, const int* in_sizes, int n_in,
                              void* d_out, int out_size) {
    const float* logits  = (const float*)d_in[0];
    const int*   targets = (const int*)d_in[1];
    float*       out     = (float*)d_out;
    (void)in_sizes; (void)n_in; (void)out_size;

    ce_fused_kernel<<<GRID, BLOCK>>>(logits, targets, out);
}

// round 8
// speedup vs baseline: 1.3449x; 1.0062x over previous
#include <cuda_runtime.h>
#include <cuda_bf16.h>

// loss_i = logsumexp(x_i) - sum_c wn[t_i][c] * x_c,  wn[t][c] = w_raw(c-t)/S(t)
// w_raw(d) = MAIN (d==0), BASE + UB*2^-d (d>0), BASE (d<0)
// S(t) = MAIN + 8*BASE + UB*(1 - 2^{t-8})

static constexpr int   NUM_CLASSES = 9;
static constexpr float BASE_W = 0.1f / 9.0f;
static constexpr float MAIN_W = 0.7f;
static constexpr float UB     = 0.2f;
static constexpr int   BATCH  = 4000000;
static constexpr int   BLOCK  = 256;
static constexpr int   WARPS  = BLOCK / 32;
static constexpr int   TILE   = 32;                      // rows per warp-tile
static constexpr int   VEC4   = TILE * NUM_CLASSES / 4;  // 72 float4 per tile
static constexpr int   NTILES = BATCH / TILE;            // 125000 exactly
static constexpr int   GRID   = 148 * 6;                 // 888: exactly 6 blocks/SM
static constexpr int   NWARPS = GRID * WARPS;            // 7104

__device__ float g_partials[GRID];
__device__ int   g_count = 0;

__global__ __launch_bounds__(BLOCK)
void ce_fused_kernel(const float* __restrict__ logits,
                     const int*   __restrict__ targets,
                     float*       __restrict__ out) {
    // per-warp double-buffered tiles: 32 rows x 9 floats = 1152B (= 72 float4)
    __shared__ float4 stage[WARPS][2][VEC4];
    __shared__ float  s_wn[NUM_CLASSES * NUM_CLASSES];  // normalized labels LUT
    __shared__ float  redw[WARPS];
    __shared__ float  red2[BLOCK];
    __shared__ int    s_last;

    const int tid  = threadIdx.x;
    const int lane = tid & 31;
    const int w    = tid >> 5;

    // build wn LUT once per block
    if (tid < NUM_CLASSES * NUM_CLASSES) {
        const int t = tid / NUM_CLASSES, c = tid % NUM_CLASSES;
        const int d = c - t;
        float wr;
        if (d == 0)      wr = MAIN_W;
        else if (d > 0)  wr = BASE_W + UB * __uint_as_float((unsigned)(127 - d) << 23);
        else             wr = BASE_W;
        const float S = MAIN_W + 8.0f * BASE_W
                      + UB * (1.0f - __uint_as_float((unsigned)(119 + t) << 23));
        s_wn[tid] = wr / S;
    }
    __syncthreads();

    float acc = 0.0f;

    // prologue prefetch (gw < NTILES always: NWARPS=7104 << NTILES=125000)
    int t = blockIdx.x * WARPS + w;
    float4 r0, r1, r2 = make_float4(0.f, 0.f, 0.f, 0.f);
    {
        const float4* p = (const float4*)logits + (size_t)t * VEC4;
        r0 = __ldg(p + lane);
        r1 = __ldg(p + 32 + lane);
        if (lane < VEC4 - 64) r2 = __ldg(p + 64 + lane);
    }
    int tg = __ldg(targets + t * TILE + lane);

    int cur = 0;
    while (t < NTILES) {
        float4* buf4 = stage[w][cur];
        buf4[lane]      = r0;
        buf4[32 + lane] = r1;
        if (lane < VEC4 - 64) buf4[64 + lane] = r2;
        const int myt = tg;
        __syncwarp();

        // prefetch next tile while computing this one
        const int tn = t + NWARPS;
        if (tn < NTILES) {
            const float4* p = (const float4*)logits + (size_t)tn * VEC4;
            r0 = __ldg(p + lane);
            r1 = __ldg(p + 32 + lane);
            if (lane < VEC4 - 64) r2 = __ldg(p + 64 + lane);
            tg = __ldg(targets + tn * TILE + lane);
        }

        // each lane computes one row from smem (stride 9 -> conflict-free)
        float x[NUM_CLASSES];
        const float* rowp = (const float*)buf4 + lane * NUM_CLASSES;
        #pragma unroll
        for (int c = 0; c < NUM_CLASSES; c++) x[c] = rowp[c];

        float m = x[0];
        #pragma unroll
        for (int c = 1; c < NUM_CLASSES; c++) m = fmaxf(m, x[c]);

        const float L2E = 1.4426950408889634f;
        const float nm  = -m * L2E;
        float se = 0.0f;
        #pragma unroll
        for (int c = 0; c < NUM_CLASSES; c++) se += exp2f(fmaf(x[c], L2E, nm));
        const float lse = m + __logf(se);

        // dot with normalized labels: 9 LDS (distinct banks / broadcast) + 9 FFMA
        const float* wn = s_wn + myt * NUM_CLASSES;
        float dot = 0.0f;
        #pragma unroll
        for (int c = 0; c < NUM_CLASSES; c++) dot = fmaf(wn[c], x[c], dot);

        acc += lse - dot;

        t = tn; cur ^= 1;
    }

    // deterministic warp butterfly reduce
    #pragma unroll
    for (int off = 16; off; off >>= 1) acc += __shfl_xor_sync(0xFFFFFFFFu, acc, off);
    if (lane == 0) redw[w] = acc;
    __syncthreads();

    if (tid == 0) {
        float b = 0.0f;
        #pragma unroll
        for (int i = 0; i < WARPS; i++) b += redw[i];
        g_partials[blockIdx.x] = b;
        __threadfence();
        s_last = (atomicAdd(&g_count, 1) == GRID - 1);
    }
    __syncthreads();

    if (s_last) {
        __threadfence();  // acquire: all partials visible
        float a = 0.0f;
        for (int i = tid; i < GRID; i += BLOCK) a += g_partials[i];
        red2[tid] = a;
        __syncthreads();
        #pragma unroll
        for (int s = BLOCK / 2; s > 0; s >>= 1) {
            if (tid < s) red2[tid] += red2[tid + s];
            __syncthreads();
        }
        if (tid == 0) {
            out[0]  = red2[0] * (1.0f / (float)BATCH);
            g_count = 0;   // reset for next graph replay
        }
    }
}

extern "C" void kernel_launch(void* const* d_in, const int* in_sizes, int n_in,
                              void* d_out, int out_size) {
    const float* logits  = (const float*)d_in[0];
    const int*   targets = (const int*)d_in[1];
    float*       out     = (float*)d_out;
    (void)in_sizes; (void)n_in; (void)out_size;

    ce_fused_kernel<<<GRID, BLOCK>>>(logits, targets, out);
}

// round 9
// speedup vs baseline: 1.7005x; 1.2644x over previous
#include <cuda_runtime.h>
#include <cuda_bf16.h>
#include <cstdint>

// loss_i = logsumexp(x_i) - sum_c wn[t_i][c] * x_c,  wn[t][c] = w_raw(c-t)/S(t)

static constexpr int   NUM_CLASSES = 9;
static constexpr float BASE_W = 0.1f / 9.0f;
static constexpr float MAIN_W = 0.7f;
static constexpr float UB     = 0.2f;
static constexpr int   BATCH  = 4000000;
static constexpr int   BLOCK  = 256;
static constexpr int   WARPS  = BLOCK / 32;
static constexpr int   TILE   = 32;                 // rows per warp-tile
static constexpr int   STAGES = 4;                  // cp.async ring depth
static constexpr int   L4     = TILE * NUM_CLASSES / 4;  // 72 float4 logits / tile
static constexpr int   S4     = L4 + TILE / 4;      // 80 float4 / stage (logits + targets)
static constexpr int   NTILES = BATCH / TILE;       // 125000 exactly
static constexpr int   GRID   = 148 * 5;            // 740: exactly 5 blocks/SM
static constexpr int   NWARPS = GRID * WARPS;       // 5920

__device__ float g_partials[GRID];
__device__ int   g_count = 0;

__device__ __forceinline__ void cp16(uint32_t saddr, const void* gaddr) {
    asm volatile("cp.async.cg.shared.global [%0], [%1], 16;" :: "r"(saddr), "l"(gaddr));
}
__device__ __forceinline__ void cp_commit() {
    asm volatile("cp.async.commit_group;" ::: "memory");
}
__device__ __forceinline__ void cp_wait3() {
    asm volatile("cp.async.wait_group 3;" ::: "memory");
}

// stage layout (float4 units): [0,72) logits (32 rows x 9 floats), [72,80) targets (32 ints)
__device__ __forceinline__ void issue_stage(uint32_t sbase,
                                            const float4* __restrict__ gl,
                                            const int*    __restrict__ gt,
                                            int tile, int lane) {
    const float4* p = gl + (size_t)tile * L4;
    cp16(sbase + lane * 16,        p + lane);        // float4 0..31
    cp16(sbase + (32 + lane) * 16, p + 32 + lane);   // float4 32..63
    if (lane < 16) {
        // lanes 0-7: logits float4 64..71 ; lanes 8-15: targets float4 0..7
        const void* src = (lane < 8)
            ? (const void*)(p + 64 + lane)
            : (const void*)((const float4*)(gt + tile * TILE) + (lane - 8));
        cp16(sbase + (64 + lane) * 16, src);
    }
}

__global__ __launch_bounds__(BLOCK)
void ce_fused_kernel(const float* __restrict__ logits,
                     const int*   __restrict__ targets,
                     float*       __restrict__ out) {
    __shared__ float4 stage[WARPS][STAGES][S4];     // 40 KB
    __shared__ float  s_wn[NUM_CLASSES * NUM_CLASSES];
    __shared__ float  redw[WARPS];
    __shared__ float  red2[BLOCK];
    __shared__ int    s_last;

    const int tid  = threadIdx.x;
    const int lane = tid & 31;
    const int w    = tid >> 5;

    // build normalized-label LUT once per block
    if (tid < NUM_CLASSES * NUM_CLASSES) {
        const int t = tid / NUM_CLASSES, c = tid % NUM_CLASSES;
        const int d = c - t;
        float wr;
        if (d == 0)      wr = MAIN_W;
        else if (d > 0)  wr = BASE_W + UB * __uint_as_float((unsigned)(127 - d) << 23);
        else             wr = BASE_W;
        const float S = MAIN_W + 8.0f * BASE_W
                      + UB * (1.0f - __uint_as_float((unsigned)(119 + t) << 23));
        s_wn[tid] = wr / S;
    }

    const float4*  gl   = (const float4*)logits;
    const uint32_t sbw  = (uint32_t)__cvta_generic_to_shared(&stage[w][0][0]);
    const int      gw   = blockIdx.x * WARPS + w;

    // prologue: fill STAGES-1 stages (gw + 2*NWARPS < NTILES always: 17760 < 125000)
    #pragma unroll
    for (int s = 0; s < STAGES - 1; s++) {
        issue_stage(sbw + s * (S4 * 16), gl, targets, gw + s * NWARPS, lane);
        cp_commit();
    }
    __syncthreads();   // LUT ready (also orders nothing harmful for cp.async)

    float acc = 0.0f;
    int t = gw, slot = 0;
    while (t < NTILES) {
        // issue stage t+3*NWARPS into slot (slot+3)&3; always commit (group bookkeeping)
        const int t3 = t + (STAGES - 1) * NWARPS;
        if (t3 < NTILES)
            issue_stage(sbw + ((slot + STAGES - 1) & (STAGES - 1)) * (S4 * 16),
                        gl, targets, t3, lane);
        cp_commit();
        cp_wait3();        // stage for t complete
        __syncwarp();      // cross-lane visibility of staged data

        const float* rowp = (const float*)(&stage[w][slot][0]) + lane * NUM_CLASSES;
        const int    myt  = ((const int*)(&stage[w][slot][L4]))[lane];

        float x[NUM_CLASSES];
        #pragma unroll
        for (int c = 0; c < NUM_CLASSES; c++) x[c] = rowp[c];

        float m = x[0];
        #pragma unroll
        for (int c = 1; c < NUM_CLASSES; c++) m = fmaxf(m, x[c]);

        const float L2E = 1.4426950408889634f;
        const float nm  = -m * L2E;
        float se = 0.0f;
        #pragma unroll
        for (int c = 0; c < NUM_CLASSES; c++) se += exp2f(fmaf(x[c], L2E, nm));
        const float lse = m + __logf(se);

        const float* wn = s_wn + myt * NUM_CLASSES;
        float dot = 0.0f;
        #pragma unroll
        for (int c = 0; c < NUM_CLASSES; c++) dot = fmaf(wn[c], x[c], dot);

        acc += lse - dot;

        __syncwarp();      // all lanes done reading slot before it is re-issued
        t += NWARPS; slot = (slot + 1) & (STAGES - 1);
    }

    // deterministic warp butterfly reduce
    #pragma unroll
    for (int off = 16; off; off >>= 1) acc += __shfl_xor_sync(0xFFFFFFFFu, acc, off);
    if (lane == 0) redw[w] = acc;
    __syncthreads();

    if (tid == 0) {
        float b = 0.0f;
        #pragma unroll
        for (int i = 0; i < WARPS; i++) b += redw[i];
        g_partials[blockIdx.x] = b;
        __threadfence();
        s_last = (atomicAdd(&g_count, 1) == GRID - 1);
    }
    __syncthreads();

    if (s_last) {
        __threadfence();  // acquire: all partials visible
        float a = 0.0f;
        for (int i = tid; i < GRID; i += BLOCK) a += g_partials[i];
        red2[tid] = a;
        __syncthreads();
        #pragma unroll
        for (int s = BLOCK / 2; s > 0; s >>= 1) {
            if (tid < s) red2[tid] += red2[tid + s];
            __syncthreads();
        }
        if (tid == 0) {
            out[0]  = red2[0] * (1.0f / (float)BATCH);
            g_count = 0;   // reset for next graph replay
        }
    }
}

extern "C" void kernel_launch(void* const* d_in, const int* in_sizes, int n_in,
                              void* d_out, int out_size) {
    const float* logits  = (const float*)d_in[0];
    const int*   targets = (const int*)d_in[1];
    float*       out     = (float*)d_out;
    (void)in_sizes; (void)n_in; (void)out_size;

    ce_fused_kernel<<<GRID, BLOCK>>>(logits, targets, out);
}